// round 12
// baseline (speedup 1.0000x reference)
#include <cuda_runtime.h>
#include <math.h>
#include <stdint.h>

// ---------------- problem constants ----------------
#define CC   256
#define HH   128
#define WW   128
#define NB   4
#define HWW  (HH*WW)
#define KTOP 100
#define KTOT (CC*9)          // 2304
#define CHUNK 64
#define NCHUNK (KTOT/CHUNK)  // 36

// output layout
#define PF_ELEMS (NB*KTOP*CC)
#define PA_OFF   PF_ELEMS
#define SC_OFF   (PF_ELEMS + NB*KTOP*11)

// dynamic smem layout (bytes)
// s_A: [128 oc][132 words]  (word 2k = hi(k), 2k+1 = lo(k)), 67584 B
// s_B: [128 px][132 words]  same interleave over k,        67584 B
// s_raw: 9 ic x 3 rows x 128 floats = 13824 B
#define OFF_A    0
#define OFF_B    67584
#define OFF_RAW  135168
#define OFF_LUT  148992     // 64 ints
#define OFF_SCL  149248     // 128 f
#define OFF_BI   149760     // 128 f
#define OFF_W2   150272     // 128 f
#define SMEM_SZ  150784

// ---------------- scratch ----------------
__device__ float g_feat[(size_t)NB*CC*HWW];
__device__ float g_plog[2*NB*HWW];
__device__ int   g_tidx[NB*KTOP];

// ---------------- helpers ----------------
__device__ __forceinline__ uint32_t smem_u32(const void* p) {
    uint32_t a;
    asm("{ .reg .u64 t; cvta.to.shared.u64 t, %1; cvt.u32.u64 %0, t; }" : "=r"(a) : "l"(p));
    return a;
}
// exact tf32 2-split: v = h + l (h: 11-bit mantissa; l covers next 11+ bits)
__device__ __forceinline__ void split2(float v, uint32_t& h, uint32_t& l) {
    uint32_t hb;
    asm("cvt.rna.tf32.f32 %0, %1;" : "=r"(hb) : "f"(v));
    float r = v - __uint_as_float(hb);
    uint32_t lb;
    asm("cvt.rna.tf32.f32 %0, %1;" : "=r"(lb) : "f"(r));
    h = hb; l = lb;
}
__device__ __forceinline__ void lds2(uint32_t& x, uint32_t& y, uint32_t a) {
    asm volatile("ld.shared.v2.b32 {%0,%1}, [%2];" : "=r"(x), "=r"(y) : "r"(a));
}
__device__ __forceinline__ void sts2(uint32_t a, uint32_t x, uint32_t y) {
    asm volatile("st.shared.v2.b32 [%0], {%1,%2};" :: "r"(a), "r"(x), "r"(y) : "memory");
}
// m16n8k8 tf32 MMA, D = A*B + D (fp32 accum in registers)
__device__ __forceinline__ void mma8(float* c, const uint32_t* a, uint32_t b0, uint32_t b1) {
    asm volatile("mma.sync.aligned.m16n8k8.row.col.f32.tf32.tf32.f32 "
        "{%0,%1,%2,%3}, {%4,%5,%6,%7}, {%8,%9}, {%0,%1,%2,%3};"
        : "+f"(c[0]), "+f"(c[1]), "+f"(c[2]), "+f"(c[3])
        : "r"(a[0]), "r"(a[1]), "r"(a[2]), "r"(a[3]), "r"(b0), "r"(b1));
}

// ---------------- conv3x3 as im2col GEMM on mma.sync tf32 ----------------
// CTA: (y row, oc half oh, batch b). M=128 oc x N=128 px x K=2304.
// Warp (8): ocq = wid>>1 (32-oc block), nq = wid&1 (64-px block).
// MODE 0: g_feat = relu(bn1(conv(bev, shared_w)))
// MODE 1: g_plog[oh] = sum_oc relu(bn2(conv(g_feat, obj_w1)))[oc] * w2[oc]
template<int MODE>
__global__ __launch_bounds__(256, 1)
void conv_mma(const float* __restrict__ in, const float* __restrict__ wgt,
              const float* __restrict__ bg, const float* __restrict__ bb,
              const float* __restrict__ bmn, const float* __restrict__ bv,
              const float* __restrict__ w2)
{
    extern __shared__ __align__(16) char smem[];
    const uint32_t sbA = smem_u32(smem) + OFF_A;
    const uint32_t sbB = smem_u32(smem) + OFF_B;
    float* s_A   = (float*)(smem + OFF_A);
    float* s_raw = (float*)(smem + OFF_RAW);
    int*   s_lut = (int*)(smem + OFF_LUT);
    float* s_scl = (float*)(smem + OFF_SCL);
    float* s_bi  = (float*)(smem + OFF_BI);
    float* s_w2s = (float*)(smem + OFF_W2);

    const int tx = threadIdx.x;
    const int y = blockIdx.x, oh = blockIdx.y, b = blockIdx.z;
    const int lane = tx & 31, wid = tx >> 5;
    const int ocq = wid >> 1, nq = wid & 1;
    const int g = lane >> 2, tig = lane & 3;

    const float* inb = (MODE == 0 ? in : (const float*)g_feat) + (size_t)b * CC * HWW;
    const float* wb  = wgt + (size_t)oh * 128 * KTOT;

    float acc[2][8][4];
    #pragma unroll
    for (int mt = 0; mt < 2; mt++)
        #pragma unroll
        for (int nt = 0; nt < 8; nt++)
            #pragma unroll
            for (int j = 0; j < 4; j++) acc[mt][nt][j] = 0.f;

    if (tx < 128) {
        int oc = oh*128 + tx;
        float scl = bg[oc] * rsqrtf(bv[oc] + 1e-5f);
        s_scl[tx] = scl;
        s_bi[tx]  = bb[oc] - bmn[oc] * scl;
        s_w2s[tx] = (MODE == 1) ? w2[oc] : 0.f;
    }

    #pragma unroll 1
    for (int c = 0; c < NCHUNK; c++) {
        const int k0 = c * CHUNK;
        const int ic_lo = k0 / 9;
        __syncthreads();                       // prior compute done with smem

        if (tx < 64) {
            int kg = k0 + tx; int ic = kg / 9; int t = kg - ic*9;
            s_lut[tx] = (ic - ic_lo) | ((t/3) << 8) | ((t%3) << 16);
        }
        // raw input: up to 9 ics x 3 rows x 128
        #pragma unroll
        for (int i = 0; i < 14; i++) {
            int e = tx + 256*i;
            if (e < 3456) {
                int ic = e / 384, rem = e - ic*384, ry = rem >> 7, x = rem & 127;
                int gy = y + ry - 1, icg = ic_lo + ic;
                float v = 0.f;
                if ((unsigned)gy < (unsigned)HH && icg < CC)
                    v = inb[((size_t)icg * HH + gy) * WW + x];
                s_raw[(ic*3 + ry)*128 + x] = v;
            }
        }
        // A (weights): [oc][2k interleave hi/lo]
        #pragma unroll
        for (int i = 0; i < 8; i++) {
            int e = tx + 256*i;                 // 2048 quads
            int oc = e >> 4, kq = e & 15;
            float4 w4 = *(const float4*)(wb + (size_t)oc * KTOT + k0 + 4*kq);
            float vs[4] = {w4.x, w4.y, w4.z, w4.w};
            #pragma unroll
            for (int jj = 0; jj < 4; jj++) {
                uint32_t hb, lb; split2(vs[jj], hb, lb);
                sts2(sbA + (oc*132 + 8*kq + 2*jj)*4, hb, lb);
            }
        }
        __syncthreads();                       // raw ready before gather

        // B (im2col): [px][2k interleave hi/lo]
        #pragma unroll 4
        for (int i = 0; i < 32; i++) {
            int e = tx + 256*i;                 // 8192 = 64 k x 128 n
            int k = e >> 7, n = e & 127;
            int lut = s_lut[k];                 // warp-uniform
            int icl = lut & 255, dy = (lut >> 8) & 255, dx = lut >> 16;
            int xx = n + dx - 1;
            float v = ((unsigned)xx < 128u) ? s_raw[(icl*3 + dy)*128 + xx] : 0.f;
            uint32_t hb, lb; split2(v, hb, lb);
            sts2(sbB + (n*132 + 2*k)*4, hb, lb);
        }
        __syncthreads();

        // compute: 8 k8-steps; per step: A frags (2 m-tiles), 8 n-tiles x 3 passes
        #pragma unroll 1
        for (int ks = 0; ks < 8; ks++) {
            uint32_t Ah[2][4], Al[2][4];
            #pragma unroll
            for (int mt = 0; mt < 2; mt++) {
                int ocr = ocq*32 + mt*16 + g;
                uint32_t base0 = sbA + (ocr*132     + 16*ks + 2*tig)*4;
                uint32_t base1 = sbA + ((ocr+8)*132 + 16*ks + 2*tig)*4;
                lds2(Ah[mt][0], Al[mt][0], base0);
                lds2(Ah[mt][2], Al[mt][2], base0 + 32);   // k+4
                lds2(Ah[mt][1], Al[mt][1], base1);
                lds2(Ah[mt][3], Al[mt][3], base1 + 32);
            }
            #pragma unroll
            for (int nt = 0; nt < 8; nt++) {
                int nb = nq*64 + nt*8 + g;
                uint32_t Bh0, Bl0, Bh1, Bl1;
                uint32_t bbase = sbB + (nb*132 + 16*ks + 2*tig)*4;
                lds2(Bh0, Bl0, bbase);
                lds2(Bh1, Bl1, bbase + 32);               // k+4
                #pragma unroll
                for (int mt = 0; mt < 2; mt++) {
                    mma8(acc[mt][nt], Ah[mt], Bh0, Bh1);  // hh
                    mma8(acc[mt][nt], Ah[mt], Bl0, Bl1);  // hl
                    mma8(acc[mt][nt], Al[mt], Bh0, Bh1);  // lh
                }
            }
        }
    }

    // ---------------- epilogue ----------------
    __syncthreads();                           // all compute done; reuse s_A
    float* s_ep = s_A;                          // [128 oc][132 px]
    #pragma unroll
    for (int mt = 0; mt < 2; mt++) {
        #pragma unroll
        for (int nt = 0; nt < 8; nt++) {
            int px0 = nq*64 + nt*8 + 2*tig;
            #pragma unroll
            for (int hrow = 0; hrow < 2; hrow++) {
                int ocr = ocq*32 + mt*16 + g + 8*hrow;
                float scl = s_scl[ocr], bi = s_bi[ocr];
                float v0 = fmaxf(acc[mt][nt][2*hrow + 0]*scl + bi, 0.f);
                float v1 = fmaxf(acc[mt][nt][2*hrow + 1]*scl + bi, 0.f);
                if (MODE == 1) { float wv = s_w2s[ocr]; v0 *= wv; v1 *= wv; }
                s_ep[ocr*132 + px0]     = v0;
                s_ep[ocr*132 + px0 + 1] = v1;
            }
        }
    }
    __syncthreads();

    if (MODE == 0) {
        #pragma unroll 8
        for (int i = 0; i < 64; i++) {
            int e = tx + 256*i;
            int m = e >> 7, x = e & 127;
            g_feat[((size_t)b*CC + oh*128 + m)*HWW + (size_t)y*WW + x] = s_ep[m*132 + x];
        }
    } else {
        if (tx < 128) {
            float s = 0.f;
            #pragma unroll 8
            for (int m = 0; m < 128; m++) s += s_ep[m*132 + tx];   // fixed order
            g_plog[((size_t)oh*NB + b)*HWW + (size_t)y*WW + tx] = s;
        }
    }
}

// ---------------- top-k (exact jax.lax.top_k semantics) ----------------
__global__ __launch_bounds__(1024)
void topk_kernel(const float* __restrict__ b2, float* __restrict__ out_sc)
{
    const int b    = blockIdx.x;
    const int tx   = threadIdx.x;
    const int lane = tx & 31, warp = tx >> 5;

    unsigned long long key[16];
    float lg[16];
    unsigned live = 0xFFFFu;
    const float bias = b2[0];

    #pragma unroll
    for (int k = 0; k < 16; k++) {
        int pix = tx + 1024*k;
        float v = g_plog[(0*NB + b)*HWW + pix] + g_plog[(1*NB + b)*HWW + pix] + bias;
        lg[k] = v;
        unsigned u = __float_as_uint(v);
        u = (u & 0x80000000u) ? ~u : (u | 0x80000000u);
        key[k] = ((unsigned long long)u << 32) | (unsigned)(0xFFFFFFFFu - (unsigned)pix);
    }

    __shared__ unsigned long long s_wmax[32];
    __shared__ unsigned long long s_best;

    for (int r = 0; r < KTOP; r++) {
        unsigned long long m = 0ull;
        #pragma unroll
        for (int k = 0; k < 16; k++)
            if (live & (1u << k)) { if (key[k] > m) m = key[k]; }
        #pragma unroll
        for (int off = 16; off; off >>= 1) {
            unsigned long long o2 = __shfl_down_sync(0xFFFFFFFFu, m, off);
            if (o2 > m) m = o2;
        }
        if (lane == 0) s_wmax[warp] = m;
        __syncthreads();
        if (warp == 0) {
            unsigned long long mm = s_wmax[lane];
            #pragma unroll
            for (int off = 16; off; off >>= 1) {
                unsigned long long o2 = __shfl_down_sync(0xFFFFFFFFu, mm, off);
                if (o2 > mm) mm = o2;
            }
            if (lane == 0) s_best = mm;
        }
        __syncthreads();
        unsigned long long best = s_best;
        #pragma unroll
        for (int k = 0; k < 16; k++) {
            if ((live & (1u << k)) && key[k] == best) {
                live &= ~(1u << k);
                int pix = tx + 1024*k;
                g_tidx[b*KTOP + r]  = pix;
                out_sc[b*KTOP + r] = 1.0f / (1.0f + expf(-lg[k]));
            }
        }
        __syncthreads();
    }
}

// ---------------- per-query head ----------------
__global__ __launch_bounds__(256)
void head_kernel(const float* __restrict__ anchors,
                 const float* __restrict__ w1, const float* __restrict__ b1,
                 const float* __restrict__ lng, const float* __restrict__ lnb,
                 const float* __restrict__ w2, const float* __restrict__ b2,
                 const float* __restrict__ zw, const float* __restrict__ zb,
                 const float* __restrict__ dw, const float* __restrict__ db,
                 const float* __restrict__ yw, const float* __restrict__ yb,
                 const float* __restrict__ vw, const float* __restrict__ vb,
                 float* __restrict__ out_pf, float* __restrict__ out_pa,
                 const float* __restrict__ out_sc)
{
    const int q = blockIdx.x;
    const int b = q / KTOP, kq = q - b*KTOP;
    const int tx = threadIdx.x, lane = tx & 31, warp = tx >> 5;

    __shared__ float s_g[CC], s_x[CC], s_h[8], s_red[16];

    const int idx = g_tidx[q];
    s_g[tx] = g_feat[((size_t)b*CC + tx)*HWW + idx];
    __syncthreads();

    for (int jj = 0; jj < 32; jj++) {
        int j = warp*32 + jj;
        const float* wr = w1 + (size_t)j*CC;
        float pp = 0.f;
        #pragma unroll
        for (int m2 = 0; m2 < 8; m2++) pp += wr[lane + 32*m2] * s_g[lane + 32*m2];
        #pragma unroll
        for (int off = 16; off; off >>= 1) pp += __shfl_down_sync(0xFFFFFFFFu, pp, off);
        if (lane == 0) s_x[j] = pp + b1[j];
    }
    __syncthreads();

    float v = s_x[tx];
    float s1 = v, s2 = v*v;
    #pragma unroll
    for (int off = 16; off; off >>= 1) {
        s1 += __shfl_xor_sync(0xFFFFFFFFu, s1, off);
        s2 += __shfl_xor_sync(0xFFFFFFFFu, s2, off);
    }
    if (lane == 0) { s_red[warp] = s1; s_red[8 + warp] = s2; }
    __syncthreads();
    float t1 = 0.f, t2 = 0.f;
    #pragma unroll
    for (int w3 = 0; w3 < 8; w3++) { t1 += s_red[w3]; t2 += s_red[8 + w3]; }
    float mu  = t1 * (1.0f/CC);
    float var = t2 * (1.0f/CC) - mu*mu;
    float rstd = rsqrtf(var + 1e-5f);
    float xn = (v - mu) * rstd * lng[tx] + lnb[tx];
    __syncthreads();
    s_x[tx] = fmaxf(xn, 0.f);
    __syncthreads();

    float sc = 1.f + out_sc[q];
    for (int jj = 0; jj < 32; jj++) {
        int j = warp*32 + jj;
        const float* wr = w2 + (size_t)j*CC;
        float pp = 0.f;
        #pragma unroll
        for (int m2 = 0; m2 < 8; m2++) pp += wr[lane + 32*m2] * s_x[lane + 32*m2];
        #pragma unroll
        for (int off = 16; off; off >>= 1) pp += __shfl_down_sync(0xFFFFFFFFu, pp, off);
        if (lane == 0) out_pf[(size_t)q*CC + j] = (pp + b2[j]) * sc;
    }

    const float* hw; float hb;
    if (warp == 0)      { hw = zw;                  hb = zb[0]; }
    else if (warp < 4)  { hw = dw + (warp-1)*CC;    hb = db[warp-1]; }
    else if (warp < 6)  { hw = yw + (warp-4)*CC;    hb = yb[warp-4]; }
    else                { hw = vw + (warp-6)*CC;    hb = vb[warp-6]; }
    float pp = 0.f;
    #pragma unroll
    for (int m2 = 0; m2 < 8; m2++) pp += hw[lane + 32*m2] * s_g[lane + 32*m2];
    #pragma unroll
    for (int off = 16; off; off >>= 1) pp += __shfl_down_sync(0xFFFFFFFFu, pp, off);
    if (lane == 0) s_h[warp] = pp + hb;
    __syncthreads();

    if (tx == 0) {
        const float* pa = anchors + ((size_t)b*900 + kq)*11;
        float zp = s_h[0];
        float d0 = s_h[1], d1 = s_h[2], d2 = s_h[3];
        float y0 = tanhf(s_h[4]), y1 = tanhf(s_h[5]);
        float nrm = fmaxf(sqrtf(y0*y0 + y1*y1), 1e-6f);
        float ve0 = s_h[6], ve1 = s_h[7];
        int xs = idx & (WW-1), ys = idx >> 7;
        float* oa = out_pa + (size_t)q*11;
        oa[0]  = ((float)xs + 0.5f) * 0.8f + (-51.2f);
        oa[1]  = ((float)ys + 0.5f) * 0.8f + (-51.2f);
        oa[2]  = pa[2] + 0.5f * zp;
        oa[3]  = pa[3] + 0.2f * fminf(fmaxf(d0, -1.f), 1.f);
        oa[4]  = pa[4] + 0.2f * fminf(fmaxf(d1, -1.f), 1.f);
        oa[5]  = pa[5] + 0.2f * fminf(fmaxf(d2, -1.f), 1.f);
        oa[6]  = 0.7f*pa[6] + 0.3f*(y0 / nrm);
        oa[7]  = 0.7f*pa[7] + 0.3f*(y1 / nrm);
        oa[8]  = pa[8] + 0.2f * fminf(fmaxf(ve0, -2.f), 2.f);
        oa[9]  = pa[9] + 0.2f * fminf(fmaxf(ve1, -2.f), 2.f);
        oa[10] = pa[10];
    }
}

// ---------------- launch ----------------
extern "C" void kernel_launch(void* const* d_in, const int* in_sizes, int n_in,
                              void* d_out, int out_size)
{
    const float* bev      = (const float*)d_in[0];
    const float* anchors  = (const float*)d_in[1];
    const float* shared_w = (const float*)d_in[2];
    const float* bn1g = (const float*)d_in[3];
    const float* bn1b = (const float*)d_in[4];
    const float* bn1m = (const float*)d_in[5];
    const float* bn1v = (const float*)d_in[6];
    const float* obj_w1 = (const float*)d_in[7];
    const float* bn2g = (const float*)d_in[8];
    const float* bn2b = (const float*)d_in[9];
    const float* bn2m = (const float*)d_in[10];
    const float* bn2v = (const float*)d_in[11];
    const float* obj_w2 = (const float*)d_in[12];
    const float* obj_b2 = (const float*)d_in[13];
    const float* fp_w1  = (const float*)d_in[14];
    const float* fp_b1  = (const float*)d_in[15];
    const float* ln_g   = (const float*)d_in[16];
    const float* ln_b   = (const float*)d_in[17];
    const float* fp_w2  = (const float*)d_in[18];
    const float* fp_b2  = (const float*)d_in[19];
    const float* z_w    = (const float*)d_in[20];
    const float* z_b    = (const float*)d_in[21];
    const float* dim_w  = (const float*)d_in[22];
    const float* dim_b  = (const float*)d_in[23];
    const float* yaw_w  = (const float*)d_in[24];
    const float* yaw_b  = (const float*)d_in[25];
    const float* vel_w  = (const float*)d_in[26];
    const float* vel_b  = (const float*)d_in[27];

    float* out    = (float*)d_out;
    float* out_pf = out;
    float* out_pa = out + PA_OFF;
    float* out_sc = out + SC_OFF;

    cudaFuncSetAttribute(conv_mma<0>, cudaFuncAttributeMaxDynamicSharedMemorySize, SMEM_SZ);
    cudaFuncSetAttribute(conv_mma<1>, cudaFuncAttributeMaxDynamicSharedMemorySize, SMEM_SZ);

    dim3 cgrid(HH, 2, NB);
    conv_mma<0><<<cgrid, 256, SMEM_SZ>>>(bev, shared_w, bn1g, bn1b, bn1m, bn1v, nullptr);
    conv_mma<1><<<cgrid, 256, SMEM_SZ>>>(nullptr, obj_w1, bn2g, bn2b, bn2m, bn2v, obj_w2);
    topk_kernel<<<NB, 1024>>>(obj_b2, out_sc);
    head_kernel<<<NB*KTOP, 256>>>(anchors, fp_w1, fp_b1, ln_g, ln_b, fp_w2, fp_b2,
                                  z_w, z_b, dim_w, dim_b, yaw_w, yaw_b, vel_w, vel_b,
                                  out_pf, out_pa, out_sc);
}

// round 15
// speedup vs baseline: 2.4775x; 2.4775x over previous
#include <cuda_runtime.h>
#include <math.h>
#include <stdint.h>

// ---------------- problem constants ----------------
#define CC   256
#define HH   128
#define WW   128
#define NB   4
#define HWW  (HH*WW)
#define KTOP 100
#define NTIL 4096                 // 64x64 tiles per image
#define TJN  (NB*NTIL)            // 16384 tile-columns
#define PPL  ((size_t)CC*TJN)     // 4,194,304 floats per position plane

// output layout
#define PF_ELEMS (NB*KTOP*CC)
#define PA_OFF   PF_ELEMS
#define SC_OFF   (PF_ELEMS + NB*KTOP*11)

typedef unsigned long long ull;

// ---------------- scratch ----------------
__device__ float g_U[16*CC*CC];          // 4 MB   [p][oc][ic]
__device__ float g_V[16*CC*TJN];         // 256 MB [p][ic][tj]
__device__ float g_M[16*CC*TJN];         // 256 MB [p][oc][tj]
__device__ float g_H[(size_t)CC*NB*HWW]; // 64 MB  [oc][b][pix] (relu*w2)
__device__ float g_feat[(size_t)NB*CC*HWW];
__device__ float g_plog[NB*HWW];
__device__ int   g_tidx[NB*KTOP];

// ---------------- helpers ----------------
__device__ __forceinline__ ull ffma2(ull a, ull b, ull c) {
    ull d;
    asm("fma.rn.f32x2 %0, %1, %2, %3;" : "=l"(d) : "l"(a), "l"(b), "l"(c));
    return d;
}
__device__ __forceinline__ ull dupf(float v) {
    unsigned u = __float_as_uint(v);
    return ((ull)u << 32) | u;
}
__device__ __forceinline__ float lo32(ull a) { return __uint_as_float((unsigned)a); }
__device__ __forceinline__ float hi32(ull a) { return __uint_as_float((unsigned)(a >> 32)); }

// ---------------- K0: weight transform U = G g G^T ----------------
__global__ __launch_bounds__(256)
void wino_wg(const float* __restrict__ w)   // [256 oc][256 ic][3][3]
{
    int idx = blockIdx.x*256 + threadIdx.x;  // oc*256+ic
    const float* g = w + (size_t)idx*9;
    float q[9];
    #pragma unroll
    for (int i = 0; i < 9; i++) q[i] = g[i];
    float t[4][3];
    #pragma unroll
    for (int j = 0; j < 3; j++) {
        float a = q[j], bqq = q[3+j], cq = q[6+j];
        t[0][j] = a;
        t[1][j] = 0.5f*(a + bqq + cq);
        t[2][j] = 0.5f*(a - bqq + cq);
        t[3][j] = cq;
    }
    #pragma unroll
    for (int i = 0; i < 4; i++) {
        float a = t[i][0], bqq = t[i][1], cq = t[i][2];
        float u0 = a, u1 = 0.5f*(a + bqq + cq), u2 = 0.5f*(a - bqq + cq), u3 = cq;
        g_U[(size_t)(4*i+0)*65536 + idx] = u0;
        g_U[(size_t)(4*i+1)*65536 + idx] = u1;
        g_U[(size_t)(4*i+2)*65536 + idx] = u2;
        g_U[(size_t)(4*i+3)*65536 + idx] = u3;
    }
}

// ---------------- K1: input transform V = B^T d B ----------------
// MODE 0: read from `in` (bev).  MODE 1: read g_feat (device symbol resolved in DEVICE code).
template<int MODE>
__global__ __launch_bounds__(256)
void wino_in(const float* __restrict__ in)  // [b][ic][128][128] (plane = b*256+ic)
{
    int idx = blockIdx.x*256 + threadIdx.x;  // 4,194,304
    int tile = idx & 4095;
    int plane = idx >> 12;                   // b*256+ic
    int ty = tile >> 6, tx6 = tile & 63;
    int b = plane >> 8, ic = plane & 255;
    const float* base_in = (MODE == 0) ? in : (const float*)g_feat;
    const float* src = base_in + (size_t)plane * HWW;
    int y0 = 2*ty - 1, x0 = 2*tx6 - 1;
    float d[4][4];
    #pragma unroll
    for (int r = 0; r < 4; r++) {
        int y = y0 + r;
        #pragma unroll
        for (int c2 = 0; c2 < 4; c2++) {
            int x = x0 + c2;
            d[r][c2] = ((unsigned)y < 128u && (unsigned)x < 128u) ? src[y*WW + x] : 0.f;
        }
    }
    float t[4][4];
    #pragma unroll
    for (int c2 = 0; c2 < 4; c2++) {
        t[0][c2] = d[0][c2] - d[2][c2];
        t[1][c2] = d[1][c2] + d[2][c2];
        t[2][c2] = d[2][c2] - d[1][c2];
        t[3][c2] = d[1][c2] - d[3][c2];
    }
    size_t tj = (size_t)b*NTIL + tile;
    #pragma unroll
    for (int i = 0; i < 4; i++) {
        float v0 = t[i][0] - t[i][2];
        float v1 = t[i][1] + t[i][2];
        float v2 = t[i][2] - t[i][1];
        float v3 = t[i][1] - t[i][3];
        g_V[(size_t)(4*i+0)*PPL + (size_t)ic*TJN + tj] = v0;
        g_V[(size_t)(4*i+1)*PPL + (size_t)ic*TJN + tj] = v1;
        g_V[(size_t)(4*i+2)*PPL + (size_t)ic*TJN + tj] = v2;
        g_V[(size_t)(4*i+3)*PPL + (size_t)ic*TJN + tj] = v3;
    }
}

// ---------------- K2: 16 batched GEMMs M[p] = U[p] @ V[p] (FFMA2 core) -----
// CTA: 64 oc x 256 tj, K=256. grid (tb=64, ocb=4, p=16).
__global__ __launch_bounds__(256, 2)
void wino_gemm()
{
    // explicit aligned layout: s_V (32768 B of ull) then s_U (4096 B of float)
    __shared__ __align__(16) char sbuf[16*256*8 + 16*64*4];
    ull*   s_V = (ull*)sbuf;
    float* s_U = (float*)(sbuf + 16*256*8);

    const int tx = threadIdx.x;
    const int tb = blockIdx.x, ocb = blockIdx.y, p = blockIdx.z;
    const int lane = tx & 31, wid = tx >> 5;
    const int ocq = wid & 3, ph = wid >> 2;

    ull acc[8][4];
    #pragma unroll
    for (int j = 0; j < 8; j++)
        #pragma unroll
        for (int kk = 0; kk < 4; kk++) acc[j][kk] = 0ull;

    const size_t pV = (size_t)p * PPL;
    const size_t pU = (size_t)p * 65536;

    #pragma unroll 1
    for (int kc = 0; kc < 16; kc++) {
        __syncthreads();
        #pragma unroll
        for (int k = 0; k < 16; k++) {
            float v = g_V[pV + (size_t)(kc*16 + k)*TJN + tb*256 + tx];
            s_V[k*256 + tx] = dupf(v);
        }
        #pragma unroll
        for (int i = 0; i < 4; i++) {
            int oc = (tx >> 4) + 16*i, k = tx & 15;
            s_U[k*64 + oc] = g_U[pU + (size_t)(ocb*64 + oc)*256 + kc*16 + k];
        }
        __syncthreads();

        #pragma unroll
        for (int k = 0; k < 16; k++) {
            // 8 weight oc-pairs as LDS.64 (8B-aligned; broadcast)
            ull w2p[8];
            const ull* wq = (const ull*)&s_U[k*64 + ocq*16];
            #pragma unroll
            for (int j = 0; j < 8; j++) w2p[j] = wq[j];
            #pragma unroll
            for (int kk = 0; kk < 4; kk++) {
                ull iv = s_V[k*256 + ph*128 + lane + 32*kk];
                #pragma unroll
                for (int j = 0; j < 8; j++)
                    acc[j][kk] = ffma2(iv, w2p[j], acc[j][kk]);
            }
        }
    }

    #pragma unroll
    for (int j = 0; j < 8; j++) {
        #pragma unroll
        for (int h = 0; h < 2; h++) {
            int oc = ocb*64 + ocq*16 + 2*j + h;
            #pragma unroll
            for (int kk = 0; kk < 4; kk++) {
                float a = h ? hi32(acc[j][kk]) : lo32(acc[j][kk]);
                g_M[(size_t)p*PPL + (size_t)oc*TJN + tb*256 + ph*128 + lane + 32*kk] = a;
            }
        }
    }
}

// ---------------- K3: inverse transform Y = A^T M A + BN + ReLU ----------------
// MODE 0 -> g_feat;  MODE 1 -> g_H (relu * w2)
template<int MODE>
__global__ __launch_bounds__(256)
void wino_out(const float* __restrict__ bg, const float* __restrict__ bb,
              const float* __restrict__ bmn, const float* __restrict__ bv,
              const float* __restrict__ w2)
{
    int idx = blockIdx.x*256 + threadIdx.x;  // 4,194,304
    int tile = idx & 4095;
    int rest = idx >> 12;
    int oc = rest & 255, b = rest >> 8;
    size_t base = (size_t)oc*TJN + (size_t)b*NTIL + tile;

    float m[16];
    #pragma unroll
    for (int p = 0; p < 16; p++) m[p] = g_M[(size_t)p*PPL + base];

    float t0[4], t1[4];
    #pragma unroll
    for (int j = 0; j < 4; j++) {
        t0[j] = m[j] + m[4+j] + m[8+j];
        t1[j] = m[4+j] - m[8+j] - m[12+j];
    }
    float Y00 = t0[0] + t0[1] + t0[2];
    float Y01 = t0[1] - t0[2] - t0[3];
    float Y10 = t1[0] + t1[1] + t1[2];
    float Y11 = t1[1] - t1[2] - t1[3];

    float scl = bg[oc] * rsqrtf(bv[oc] + 1e-5f);
    float bi  = bb[oc] - bmn[oc] * scl;
    Y00 = fmaxf(Y00*scl + bi, 0.f);
    Y01 = fmaxf(Y01*scl + bi, 0.f);
    Y10 = fmaxf(Y10*scl + bi, 0.f);
    Y11 = fmaxf(Y11*scl + bi, 0.f);

    int ty = tile >> 6, tx6 = tile & 63;
    int y = 2*ty, x = 2*tx6;
    if (MODE == 0) {
        float* dst = g_feat + ((size_t)b*CC + oc)*HWW + (size_t)y*WW + x;
        *(float2*)dst          = make_float2(Y00, Y01);
        *(float2*)(dst + WW)   = make_float2(Y10, Y11);
    } else {
        float wv = w2[oc];
        float* dst = g_H + ((size_t)oc*NB + b)*HWW + (size_t)y*WW + x;
        *(float2*)dst          = make_float2(Y00*wv, Y01*wv);
        *(float2*)(dst + WW)   = make_float2(Y10*wv, Y11*wv);
    }
}

// ---------------- K4: heatmap logit = sum over oc (fixed order) ----------------
__global__ __launch_bounds__(256)
void red_kernel()
{
    int idx = blockIdx.x*256 + threadIdx.x;   // 65536
    int b = idx >> 14, pix = idx & 16383;
    float s = 0.f;
    #pragma unroll 8
    for (int oc = 0; oc < CC; oc++)
        s += g_H[((size_t)oc*NB + b)*HWW + pix];
    g_plog[b*HWW + pix] = s;
}

// ---------------- top-k (exact jax.lax.top_k semantics) ----------------
__global__ __launch_bounds__(1024)
void topk_kernel(const float* __restrict__ b2, float* __restrict__ out_sc)
{
    const int b    = blockIdx.x;
    const int tx   = threadIdx.x;
    const int lane = tx & 31, warp = tx >> 5;

    unsigned long long key[16];
    float lg[16];
    unsigned live = 0xFFFFu;
    const float bias = b2[0];

    #pragma unroll
    for (int k = 0; k < 16; k++) {
        int pix = tx + 1024*k;
        float v = g_plog[b*HWW + pix] + bias;
        lg[k] = v;
        unsigned u = __float_as_uint(v);
        u = (u & 0x80000000u) ? ~u : (u | 0x80000000u);
        key[k] = ((unsigned long long)u << 32) | (unsigned)(0xFFFFFFFFu - (unsigned)pix);
    }

    __shared__ unsigned long long s_wmax[32];
    __shared__ unsigned long long s_best;

    for (int r = 0; r < KTOP; r++) {
        unsigned long long m = 0ull;
        #pragma unroll
        for (int k = 0; k < 16; k++)
            if (live & (1u << k)) { if (key[k] > m) m = key[k]; }
        #pragma unroll
        for (int off = 16; off; off >>= 1) {
            unsigned long long o2 = __shfl_down_sync(0xFFFFFFFFu, m, off);
            if (o2 > m) m = o2;
        }
        if (lane == 0) s_wmax[warp] = m;
        __syncthreads();
        if (warp == 0) {
            unsigned long long mm = s_wmax[lane];
            #pragma unroll
            for (int off = 16; off; off >>= 1) {
                unsigned long long o2 = __shfl_down_sync(0xFFFFFFFFu, mm, off);
                if (o2 > mm) mm = o2;
            }
            if (lane == 0) s_best = mm;
        }
        __syncthreads();
        unsigned long long best = s_best;
        #pragma unroll
        for (int k = 0; k < 16; k++) {
            if ((live & (1u << k)) && key[k] == best) {
                live &= ~(1u << k);
                int pix = tx + 1024*k;
                g_tidx[b*KTOP + r]  = pix;
                out_sc[b*KTOP + r] = 1.0f / (1.0f + expf(-lg[k]));
            }
        }
        __syncthreads();
    }
}

// ---------------- per-query head ----------------
__global__ __launch_bounds__(256)
void head_kernel(const float* __restrict__ anchors,
                 const float* __restrict__ w1, const float* __restrict__ b1,
                 const float* __restrict__ lng, const float* __restrict__ lnb,
                 const float* __restrict__ w2, const float* __restrict__ b2,
                 const float* __restrict__ zw, const float* __restrict__ zb,
                 const float* __restrict__ dw, const float* __restrict__ db,
                 const float* __restrict__ yw, const float* __restrict__ yb,
                 const float* __restrict__ vw, const float* __restrict__ vb,
                 float* __restrict__ out_pf, float* __restrict__ out_pa,
                 const float* __restrict__ out_sc)
{
    const int q = blockIdx.x;
    const int b = q / KTOP, kq = q - b*KTOP;
    const int tx = threadIdx.x, lane = tx & 31, warp = tx >> 5;

    __shared__ float s_g[CC], s_x[CC], s_h[8], s_red[16];

    const int idx = g_tidx[q];
    s_g[tx] = g_feat[((size_t)b*CC + tx)*HWW + idx];
    __syncthreads();

    for (int jj = 0; jj < 32; jj++) {
        int j = warp*32 + jj;
        const float* wr = w1 + (size_t)j*CC;
        float pp = 0.f;
        #pragma unroll
        for (int m2 = 0; m2 < 8; m2++) pp += wr[lane + 32*m2] * s_g[lane + 32*m2];
        #pragma unroll
        for (int off = 16; off; off >>= 1) pp += __shfl_down_sync(0xFFFFFFFFu, pp, off);
        if (lane == 0) s_x[j] = pp + b1[j];
    }
    __syncthreads();

    float v = s_x[tx];
    float s1 = v, s2 = v*v;
    #pragma unroll
    for (int off = 16; off; off >>= 1) {
        s1 += __shfl_xor_sync(0xFFFFFFFFu, s1, off);
        s2 += __shfl_xor_sync(0xFFFFFFFFu, s2, off);
    }
    if (lane == 0) { s_red[warp] = s1; s_red[8 + warp] = s2; }
    __syncthreads();
    float t1 = 0.f, t2 = 0.f;
    #pragma unroll
    for (int w3 = 0; w3 < 8; w3++) { t1 += s_red[w3]; t2 += s_red[8 + w3]; }
    float mu  = t1 * (1.0f/CC);
    float var = t2 * (1.0f/CC) - mu*mu;
    float rstd = rsqrtf(var + 1e-5f);
    float xn = (v - mu) * rstd * lng[tx] + lnb[tx];
    __syncthreads();
    s_x[tx] = fmaxf(xn, 0.f);
    __syncthreads();

    float sc = 1.f + out_sc[q];
    for (int jj = 0; jj < 32; jj++) {
        int j = warp*32 + jj;
        const float* wr = w2 + (size_t)j*CC;
        float pp = 0.f;
        #pragma unroll
        for (int m2 = 0; m2 < 8; m2++) pp += wr[lane + 32*m2] * s_x[lane + 32*m2];
        #pragma unroll
        for (int off = 16; off; off >>= 1) pp += __shfl_down_sync(0xFFFFFFFFu, pp, off);
        if (lane == 0) out_pf[(size_t)q*CC + j] = (pp + b2[j]) * sc;
    }

    const float* hw; float hb;
    if (warp == 0)      { hw = zw;                  hb = zb[0]; }
    else if (warp < 4)  { hw = dw + (warp-1)*CC;    hb = db[warp-1]; }
    else if (warp < 6)  { hw = yw + (warp-4)*CC;    hb = yb[warp-4]; }
    else                { hw = vw + (warp-6)*CC;    hb = vb[warp-6]; }
    float pp = 0.f;
    #pragma unroll
    for (int m2 = 0; m2 < 8; m2++) pp += hw[lane + 32*m2] * s_g[lane + 32*m2];
    #pragma unroll
    for (int off = 16; off; off >>= 1) pp += __shfl_down_sync(0xFFFFFFFFu, pp, off);
    if (lane == 0) s_h[warp] = pp + hb;
    __syncthreads();

    if (tx == 0) {
        const float* pa = anchors + ((size_t)b*900 + kq)*11;
        float zp = s_h[0];
        float d0 = s_h[1], d1 = s_h[2], d2 = s_h[3];
        float y0 = tanhf(s_h[4]), y1 = tanhf(s_h[5]);
        float nrm = fmaxf(sqrtf(y0*y0 + y1*y1), 1e-6f);
        float ve0 = s_h[6], ve1 = s_h[7];
        int xs = idx & (WW-1), ys = idx >> 7;
        float* oa = out_pa + (size_t)q*11;
        oa[0]  = ((float)xs + 0.5f) * 0.8f + (-51.2f);
        oa[1]  = ((float)ys + 0.5f) * 0.8f + (-51.2f);
        oa[2]  = pa[2] + 0.5f * zp;
        oa[3]  = pa[3] + 0.2f * fminf(fmaxf(d0, -1.f), 1.f);
        oa[4]  = pa[4] + 0.2f * fminf(fmaxf(d1, -1.f), 1.f);
        oa[5]  = pa[5] + 0.2f * fminf(fmaxf(d2, -1.f), 1.f);
        oa[6]  = 0.7f*pa[6] + 0.3f*(y0 / nrm);
        oa[7]  = 0.7f*pa[7] + 0.3f*(y1 / nrm);
        oa[8]  = pa[8] + 0.2f * fminf(fmaxf(ve0, -2.f), 2.f);
        oa[9]  = pa[9] + 0.2f * fminf(fmaxf(ve1, -2.f), 2.f);
        oa[10] = pa[10];
    }
}

// ---------------- launch ----------------
extern "C" void kernel_launch(void* const* d_in, const int* in_sizes, int n_in,
                              void* d_out, int out_size)
{
    const float* bev      = (const float*)d_in[0];
    const float* anchors  = (const float*)d_in[1];
    const float* shared_w = (const float*)d_in[2];
    const float* bn1g = (const float*)d_in[3];
    const float* bn1b = (const float*)d_in[4];
    const float* bn1m = (const float*)d_in[5];
    const float* bn1v = (const float*)d_in[6];
    const float* obj_w1 = (const float*)d_in[7];
    const float* bn2g = (const float*)d_in[8];
    const float* bn2b = (const float*)d_in[9];
    const float* bn2m = (const float*)d_in[10];
    const float* bn2v = (const float*)d_in[11];
    const float* obj_w2 = (const float*)d_in[12];
    const float* obj_b2 = (const float*)d_in[13];
    const float* fp_w1  = (const float*)d_in[14];
    const float* fp_b1  = (const float*)d_in[15];
    const float* ln_g   = (const float*)d_in[16];
    const float* ln_b   = (const float*)d_in[17];
    const float* fp_w2  = (const float*)d_in[18];
    const float* fp_b2  = (const float*)d_in[19];
    const float* z_w    = (const float*)d_in[20];
    const float* z_b    = (const float*)d_in[21];
    const float* dim_w  = (const float*)d_in[22];
    const float* dim_b  = (const float*)d_in[23];
    const float* yaw_w  = (const float*)d_in[24];
    const float* yaw_b  = (const float*)d_in[25];
    const float* vel_w  = (const float*)d_in[26];
    const float* vel_b  = (const float*)d_in[27];

    float* out    = (float*)d_out;
    float* out_pf = out;
    float* out_pa = out + PA_OFF;
    float* out_sc = out + SC_OFF;

    dim3 ggrid(64, 4, 16);

    // ---- conv1: bev -> g_feat
    wino_wg<<<256, 256>>>(shared_w);
    wino_in<0><<<16384, 256>>>(bev);
    wino_gemm<<<ggrid, 256>>>();
    wino_out<0><<<16384, 256>>>(bn1g, bn1b, bn1m, bn1v, nullptr);

    // ---- conv2: g_feat -> heatmap logits (input resolved in DEVICE code)
    wino_wg<<<256, 256>>>(obj_w1);
    wino_in<1><<<16384, 256>>>(nullptr);
    wino_gemm<<<ggrid, 256>>>();
    wino_out<1><<<16384, 256>>>(bn2g, bn2b, bn2m, bn2v, obj_w2);
    red_kernel<<<256, 256>>>();

    // ---- topk + head
    topk_kernel<<<NB, 1024>>>(obj_b2, out_sc);
    head_kernel<<<NB*KTOP, 256>>>(anchors, fp_w1, fp_b1, ln_g, ln_b, fp_w2, fp_b2,
                                  z_w, z_b, dim_w, dim_b, yaw_w, yaw_b, vel_w, vel_b,
                                  out_pf, out_pa, out_sc);
}

// round 16
// speedup vs baseline: 3.8112x; 1.5383x over previous
#include <cuda_runtime.h>
#include <math.h>
#include <stdint.h>

// ---------------- problem constants ----------------
#define CC   256
#define HH   128
#define WW   128
#define NB   4
#define HWW  (HH*WW)
#define KTOP 100
#define NTIL4 1024                 // 32x32 tiles per image (4x4 outputs each)
#define TJ4   (NB*NTIL4)           // 4096 tile-columns
#define PPL4  ((size_t)CC*TJ4)     // 1,048,576 floats per plane

// output layout
#define PF_ELEMS (NB*KTOP*CC)
#define PA_OFF   PF_ELEMS
#define SC_OFF   (PF_ELEMS + NB*KTOP*11)

typedef unsigned long long ull;

// ---------------- scratch ----------------
__device__ float g_U[36*CC*CC];           // 9.4 MB  [p][oc][ic]
__device__ float g_V[36*CC*TJ4];          // 151 MB  [p][ic][tj]
__device__ float g_M[36*CC*TJ4];          // 151 MB  [p][oc][tj]
__device__ float g_H[(size_t)CC*NB*HWW];  // 67 MB   [oc][b][pix] (relu*w2)
__device__ float g_feat[(size_t)NB*CC*HWW];
__device__ float g_plog[NB*HWW];
__device__ int   g_tidx[NB*KTOP];

// ---------------- helpers ----------------
__device__ __forceinline__ ull ffma2(ull a, ull b, ull c) {
    ull d;
    asm("fma.rn.f32x2 %0, %1, %2, %3;" : "=l"(d) : "l"(a), "l"(b), "l"(c));
    return d;
}
__device__ __forceinline__ ull dupf(float v) {
    unsigned u = __float_as_uint(v);
    return ((ull)u << 32) | u;
}
__device__ __forceinline__ float lo32(ull a) { return __uint_as_float((unsigned)a); }
__device__ __forceinline__ float hi32(ull a) { return __uint_as_float((unsigned)(a >> 32)); }

// G rows (F(4,3)): [1/4,0,0] [-1/6,-1/6,-1/6] [-1/6,1/6,-1/6] [1/24,1/12,1/6] [1/24,-1/12,1/6] [0,0,1]
__device__ __forceinline__ void gmul(float a, float b, float c, float* o) {
    const float s6 = 1.f/6.f, s12 = 1.f/12.f, s24 = 1.f/24.f;
    o[0] = 0.25f*a;
    o[1] = -s6*(a + b + c);
    o[2] = -s6*(a - b + c);
    o[3] = s24*a + s12*b + s6*c;
    o[4] = s24*a - s12*b + s6*c;
    o[5] = c;
}
// BT rows: [4,0,-5,0,1,0] [0,-4,-4,1,1,0] [0,4,-4,-1,1,0] [0,-2,-1,2,1,0] [0,2,-1,-2,1,0] [0,4,0,-5,0,1]
__device__ __forceinline__ void btmul(const float* a, float* o) {
    o[0] = 4.f*a[0] - 5.f*a[2] + a[4];
    o[1] = -4.f*a[1] - 4.f*a[2] + a[3] + a[4];
    o[2] =  4.f*a[1] - 4.f*a[2] - a[3] + a[4];
    o[3] = -2.f*a[1] - a[2] + 2.f*a[3] + a[4];
    o[4] =  2.f*a[1] - a[2] - 2.f*a[3] + a[4];
    o[5] =  4.f*a[1] - 5.f*a[3] + a[5];
}
// AT rows: [1,1,1,1,1,0] [0,1,-1,2,-2,0] [0,1,1,4,4,0] [0,1,-1,8,-8,1]
__device__ __forceinline__ void atmul(const float* a, float* o) {
    o[0] = a[0] + a[1] + a[2] + a[3] + a[4];
    o[1] = a[1] - a[2] + 2.f*a[3] - 2.f*a[4];
    o[2] = a[1] + a[2] + 4.f*a[3] + 4.f*a[4];
    o[3] = a[1] - a[2] + 8.f*a[3] - 8.f*a[4] + a[5];
}

// ---------------- K0: weight transform U = G g G^T (6x6) ----------------
__global__ __launch_bounds__(256)
void wino_wg(const float* __restrict__ w)   // [256 oc][256 ic][3][3]
{
    int idx = blockIdx.x*256 + threadIdx.x;  // oc*256+ic
    const float* g = w + (size_t)idx*9;
    float q[9];
    #pragma unroll
    for (int i = 0; i < 9; i++) q[i] = g[i];
    float u[6][3];
    #pragma unroll
    for (int c = 0; c < 3; c++) {
        float col[6];
        gmul(q[c], q[3+c], q[6+c], col);
        #pragma unroll
        for (int i = 0; i < 6; i++) u[i][c] = col[i];
    }
    #pragma unroll
    for (int i = 0; i < 6; i++) {
        float row[6];
        gmul(u[i][0], u[i][1], u[i][2], row);
        #pragma unroll
        for (int j = 0; j < 6; j++)
            g_U[(size_t)(i*6+j)*65536 + idx] = row[j];
    }
}

// ---------------- K1: input transform V = B^T d B (6x6 patch, stride 4) ----
template<int MODE>
__global__ __launch_bounds__(256)
void wino_in(const float* __restrict__ in)  // [b][ic][128][128] (plane = b*256+ic)
{
    int idx = blockIdx.x*256 + threadIdx.x;  // 1,048,576
    int tile = idx & 1023;
    int plane = idx >> 10;                   // b*256+ic
    int ty = tile >> 5, tx5 = tile & 31;
    int b = plane >> 8, ic = plane & 255;
    const float* base_in = (MODE == 0) ? in : (const float*)g_feat;
    const float* src = base_in + (size_t)plane * HWW;
    int y0 = 4*ty - 1, x0 = 4*tx5 - 1;

    float d[6][6];
    #pragma unroll
    for (int r = 0; r < 6; r++) {
        int y = y0 + r;
        #pragma unroll
        for (int c2 = 0; c2 < 6; c2++) {
            int x = x0 + c2;
            d[r][c2] = ((unsigned)y < 128u && (unsigned)x < 128u) ? src[y*WW + x] : 0.f;
        }
    }
    float t[6][6];
    #pragma unroll
    for (int c2 = 0; c2 < 6; c2++) {
        float col[6] = {d[0][c2], d[1][c2], d[2][c2], d[3][c2], d[4][c2], d[5][c2]};
        float o[6];
        btmul(col, o);
        #pragma unroll
        for (int i = 0; i < 6; i++) t[i][c2] = o[i];
    }
    size_t tj = (size_t)b*NTIL4 + tile;
    #pragma unroll
    for (int i = 0; i < 6; i++) {
        float o[6];
        btmul(t[i], o);
        #pragma unroll
        for (int j = 0; j < 6; j++)
            g_V[(size_t)(i*6+j)*PPL4 + (size_t)ic*TJ4 + tj] = o[j];
    }
}

// ---------------- K2: 36 batched GEMMs M[p] = U[p] @ V[p] (FFMA2 core) -----
// CTA: 64 oc x 256 tj, K=256. grid (tb=16, ocb=4, p=36).
__global__ __launch_bounds__(256, 2)
void wino_gemm()
{
    __shared__ __align__(16) char sbuf[16*256*8 + 16*64*4];
    ull*   s_V = (ull*)sbuf;
    float* s_U = (float*)(sbuf + 16*256*8);

    const int tx = threadIdx.x;
    const int tb = blockIdx.x, ocb = blockIdx.y, p = blockIdx.z;
    const int lane = tx & 31, wid = tx >> 5;
    const int ocq = wid & 3, ph = wid >> 2;

    ull acc[8][4];
    #pragma unroll
    for (int j = 0; j < 8; j++)
        #pragma unroll
        for (int kk = 0; kk < 4; kk++) acc[j][kk] = 0ull;

    const size_t pV = (size_t)p * PPL4;
    const size_t pU = (size_t)p * 65536;

    #pragma unroll 1
    for (int kc = 0; kc < 16; kc++) {
        __syncthreads();
        #pragma unroll
        for (int k = 0; k < 16; k++) {
            float v = g_V[pV + (size_t)(kc*16 + k)*TJ4 + tb*256 + tx];
            s_V[k*256 + tx] = dupf(v);
        }
        #pragma unroll
        for (int i = 0; i < 4; i++) {
            int oc = (tx >> 4) + 16*i, k = tx & 15;
            s_U[k*64 + oc] = g_U[pU + (size_t)(ocb*64 + oc)*256 + kc*16 + k];
        }
        __syncthreads();

        #pragma unroll
        for (int k = 0; k < 16; k++) {
            ull w2p[8];
            const ull* wq = (const ull*)&s_U[k*64 + ocq*16];
            #pragma unroll
            for (int j = 0; j < 8; j++) w2p[j] = wq[j];
            #pragma unroll
            for (int kk = 0; kk < 4; kk++) {
                ull iv = s_V[k*256 + ph*128 + lane + 32*kk];
                #pragma unroll
                for (int j = 0; j < 8; j++)
                    acc[j][kk] = ffma2(iv, w2p[j], acc[j][kk]);
            }
        }
    }

    #pragma unroll
    for (int j = 0; j < 8; j++) {
        #pragma unroll
        for (int h = 0; h < 2; h++) {
            int oc = ocb*64 + ocq*16 + 2*j + h;
            #pragma unroll
            for (int kk = 0; kk < 4; kk++) {
                float a = h ? hi32(acc[j][kk]) : lo32(acc[j][kk]);
                g_M[(size_t)p*PPL4 + (size_t)oc*TJ4 + tb*256 + ph*128 + lane + 32*kk] = a;
            }
        }
    }
}

// ---------------- K3: inverse transform Y = A^T M A + BN + ReLU ----------------
// MODE 0 -> g_feat;  MODE 1 -> g_H (relu * w2)
template<int MODE>
__global__ __launch_bounds__(256)
void wino_out(const float* __restrict__ bg, const float* __restrict__ bb,
              const float* __restrict__ bmn, const float* __restrict__ bv,
              const float* __restrict__ w2)
{
    int idx = blockIdx.x*256 + threadIdx.x;  // 1,048,576
    int tile = idx & 1023;
    int rest = idx >> 10;
    int oc = rest & 255, b = rest >> 8;
    size_t base = (size_t)oc*TJ4 + (size_t)b*NTIL4 + tile;

    float m[6][6];
    #pragma unroll
    for (int r = 0; r < 6; r++)
        #pragma unroll
        for (int c2 = 0; c2 < 6; c2++)
            m[r][c2] = g_M[(size_t)(r*6+c2)*PPL4 + base];

    float t[4][6];
    #pragma unroll
    for (int c2 = 0; c2 < 6; c2++) {
        float col[6] = {m[0][c2], m[1][c2], m[2][c2], m[3][c2], m[4][c2], m[5][c2]};
        float o[4];
        atmul(col, o);
        #pragma unroll
        for (int i = 0; i < 4; i++) t[i][c2] = o[i];
    }

    float scl = bg[oc] * rsqrtf(bv[oc] + 1e-5f);
    float bi  = bb[oc] - bmn[oc] * scl;
    float wv = (MODE == 1) ? w2[oc] : 1.f;

    int ty = tile >> 5, tx5 = tile & 31;
    int y = 4*ty, x = 4*tx5;
    float* dstb = (MODE == 0)
        ? g_feat + ((size_t)b*CC + oc)*HWW + (size_t)y*WW + x
        : g_H    + ((size_t)oc*NB + b)*HWW + (size_t)y*WW + x;

    #pragma unroll
    for (int i = 0; i < 4; i++) {
        float o[4];
        atmul(t[i], o);
        float4 v;
        v.x = fmaxf(o[0]*scl + bi, 0.f);
        v.y = fmaxf(o[1]*scl + bi, 0.f);
        v.z = fmaxf(o[2]*scl + bi, 0.f);
        v.w = fmaxf(o[3]*scl + bi, 0.f);
        if (MODE == 1) { v.x *= wv; v.y *= wv; v.z *= wv; v.w *= wv; }
        *(float4*)(dstb + (size_t)i*WW) = v;
    }
}

// ---------------- K4: heatmap logit = sum over oc (fixed order) ----------------
__global__ __launch_bounds__(256)
void red_kernel()
{
    int idx = blockIdx.x*256 + threadIdx.x;   // 65536
    int b = idx >> 14, pix = idx & 16383;
    float s = 0.f;
    #pragma unroll 8
    for (int oc = 0; oc < CC; oc++)
        s += g_H[((size_t)oc*NB + b)*HWW + pix];
    g_plog[b*HWW + pix] = s;
}

// ---------------- top-k (exact jax.lax.top_k semantics) ----------------
__global__ __launch_bounds__(1024)
void topk_kernel(const float* __restrict__ b2, float* __restrict__ out_sc)
{
    const int b    = blockIdx.x;
    const int tx   = threadIdx.x;
    const int lane = tx & 31, warp = tx >> 5;

    unsigned long long key[16];
    float lg[16];
    unsigned live = 0xFFFFu;
    const float bias = b2[0];

    #pragma unroll
    for (int k = 0; k < 16; k++) {
        int pix = tx + 1024*k;
        float v = g_plog[b*HWW + pix] + bias;
        lg[k] = v;
        unsigned u = __float_as_uint(v);
        u = (u & 0x80000000u) ? ~u : (u | 0x80000000u);
        key[k] = ((unsigned long long)u << 32) | (unsigned)(0xFFFFFFFFu - (unsigned)pix);
    }

    __shared__ unsigned long long s_wmax[32];
    __shared__ unsigned long long s_best;

    for (int r = 0; r < KTOP; r++) {
        unsigned long long m = 0ull;
        #pragma unroll
        for (int k = 0; k < 16; k++)
            if (live & (1u << k)) { if (key[k] > m) m = key[k]; }
        #pragma unroll
        for (int off = 16; off; off >>= 1) {
            unsigned long long o2 = __shfl_down_sync(0xFFFFFFFFu, m, off);
            if (o2 > m) m = o2;
        }
        if (lane == 0) s_wmax[warp] = m;
        __syncthreads();
        if (warp == 0) {
            unsigned long long mm = s_wmax[lane];
            #pragma unroll
            for (int off = 16; off; off >>= 1) {
                unsigned long long o2 = __shfl_down_sync(0xFFFFFFFFu, mm, off);
                if (o2 > mm) mm = o2;
            }
            if (lane == 0) s_best = mm;
        }
        __syncthreads();
        unsigned long long best = s_best;
        #pragma unroll
        for (int k = 0; k < 16; k++) {
            if ((live & (1u << k)) && key[k] == best) {
                live &= ~(1u << k);
                int pix = tx + 1024*k;
                g_tidx[b*KTOP + r]  = pix;
                out_sc[b*KTOP + r] = 1.0f / (1.0f + expf(-lg[k]));
            }
        }
        __syncthreads();
    }
}

// ---------------- per-query head ----------------
__global__ __launch_bounds__(256)
void head_kernel(const float* __restrict__ anchors,
                 const float* __restrict__ w1, const float* __restrict__ b1,
                 const float* __restrict__ lng, const float* __restrict__ lnb,
                 const float* __restrict__ w2, const float* __restrict__ b2,
                 const float* __restrict__ zw, const float* __restrict__ zb,
                 const float* __restrict__ dw, const float* __restrict__ db,
                 const float* __restrict__ yw, const float* __restrict__ yb,
                 const float* __restrict__ vw, const float* __restrict__ vb,
                 float* __restrict__ out_pf, float* __restrict__ out_pa,
                 const float* __restrict__ out_sc)
{
    const int q = blockIdx.x;
    const int b = q / KTOP, kq = q - b*KTOP;
    const int tx = threadIdx.x, lane = tx & 31, warp = tx >> 5;

    __shared__ float s_g[CC], s_x[CC], s_h[8], s_red[16];

    const int idx = g_tidx[q];
    s_g[tx] = g_feat[((size_t)b*CC + tx)*HWW + idx];
    __syncthreads();

    for (int jj = 0; jj < 32; jj++) {
        int j = warp*32 + jj;
        const float* wr = w1 + (size_t)j*CC;
        float pp = 0.f;
        #pragma unroll
        for (int m2 = 0; m2 < 8; m2++) pp += wr[lane + 32*m2] * s_g[lane + 32*m2];
        #pragma unroll
        for (int off = 16; off; off >>= 1) pp += __shfl_down_sync(0xFFFFFFFFu, pp, off);
        if (lane == 0) s_x[j] = pp + b1[j];
    }
    __syncthreads();

    float v = s_x[tx];
    float s1 = v, s2 = v*v;
    #pragma unroll
    for (int off = 16; off; off >>= 1) {
        s1 += __shfl_xor_sync(0xFFFFFFFFu, s1, off);
        s2 += __shfl_xor_sync(0xFFFFFFFFu, s2, off);
    }
    if (lane == 0) { s_red[warp] = s1; s_red[8 + warp] = s2; }
    __syncthreads();
    float t1 = 0.f, t2 = 0.f;
    #pragma unroll
    for (int w3 = 0; w3 < 8; w3++) { t1 += s_red[w3]; t2 += s_red[8 + w3]; }
    float mu  = t1 * (1.0f/CC);
    float var = t2 * (1.0f/CC) - mu*mu;
    float rstd = rsqrtf(var + 1e-5f);
    float xn = (v - mu) * rstd * lng[tx] + lnb[tx];
    __syncthreads();
    s_x[tx] = fmaxf(xn, 0.f);
    __syncthreads();

    float sc = 1.f + out_sc[q];
    for (int jj = 0; jj < 32; jj++) {
        int j = warp*32 + jj;
        const float* wr = w2 + (size_t)j*CC;
        float pp = 0.f;
        #pragma unroll
        for (int m2 = 0; m2 < 8; m2++) pp += wr[lane + 32*m2] * s_x[lane + 32*m2];
        #pragma unroll
        for (int off = 16; off; off >>= 1) pp += __shfl_down_sync(0xFFFFFFFFu, pp, off);
        if (lane == 0) out_pf[(size_t)q*CC + j] = (pp + b2[j]) * sc;
    }

    const float* hw; float hb;
    if (warp == 0)      { hw = zw;                  hb = zb[0]; }
    else if (warp < 4)  { hw = dw + (warp-1)*CC;    hb = db[warp-1]; }
    else if (warp < 6)  { hw = yw + (warp-4)*CC;    hb = yb[warp-4]; }
    else                { hw = vw + (warp-6)*CC;    hb = vb[warp-6]; }
    float pp = 0.f;
    #pragma unroll
    for (int m2 = 0; m2 < 8; m2++) pp += hw[lane + 32*m2] * s_g[lane + 32*m2];
    #pragma unroll
    for (int off = 16; off; off >>= 1) pp += __shfl_down_sync(0xFFFFFFFFu, pp, off);
    if (lane == 0) s_h[warp] = pp + hb;
    __syncthreads();

    if (tx == 0) {
        const float* pa = anchors + ((size_t)b*900 + kq)*11;
        float zp = s_h[0];
        float d0 = s_h[1], d1 = s_h[2], d2 = s_h[3];
        float y0 = tanhf(s_h[4]), y1 = tanhf(s_h[5]);
        float nrm = fmaxf(sqrtf(y0*y0 + y1*y1), 1e-6f);
        float ve0 = s_h[6], ve1 = s_h[7];
        int xs = idx & (WW-1), ys = idx >> 7;
        float* oa = out_pa + (size_t)q*11;
        oa[0]  = ((float)xs + 0.5f) * 0.8f + (-51.2f);
        oa[1]  = ((float)ys + 0.5f) * 0.8f + (-51.2f);
        oa[2]  = pa[2] + 0.5f * zp;
        oa[3]  = pa[3] + 0.2f * fminf(fmaxf(d0, -1.f), 1.f);
        oa[4]  = pa[4] + 0.2f * fminf(fmaxf(d1, -1.f), 1.f);
        oa[5]  = pa[5] + 0.2f * fminf(fmaxf(d2, -1.f), 1.f);
        oa[6]  = 0.7f*pa[6] + 0.3f*(y0 / nrm);
        oa[7]  = 0.7f*pa[7] + 0.3f*(y1 / nrm);
        oa[8]  = pa[8] + 0.2f * fminf(fmaxf(ve0, -2.f), 2.f);
        oa[9]  = pa[9] + 0.2f * fminf(fmaxf(ve1, -2.f), 2.f);
        oa[10] = pa[10];
    }
}

// ---------------- launch ----------------
extern "C" void kernel_launch(void* const* d_in, const int* in_sizes, int n_in,
                              void* d_out, int out_size)
{
    const float* bev      = (const float*)d_in[0];
    const float* anchors  = (const float*)d_in[1];
    const float* shared_w = (const float*)d_in[2];
    const float* bn1g = (const float*)d_in[3];
    const float* bn1b = (const float*)d_in[4];
    const float* bn1m = (const float*)d_in[5];
    const float* bn1v = (const float*)d_in[6];
    const float* obj_w1 = (const float*)d_in[7];
    const float* bn2g = (const float*)d_in[8];
    const float* bn2b = (const float*)d_in[9];
    const float* bn2m = (const float*)d_in[10];
    const float* bn2v = (const float*)d_in[11];
    const float* obj_w2 = (const float*)d_in[12];
    const float* obj_b2 = (const float*)d_in[13];
    const float* fp_w1  = (const float*)d_in[14];
    const float* fp_b1  = (const float*)d_in[15];
    const float* ln_g   = (const float*)d_in[16];
    const float* ln_b   = (const float*)d_in[17];
    const float* fp_w2  = (const float*)d_in[18];
    const float* fp_b2  = (const float*)d_in[19];
    const float* z_w    = (const float*)d_in[20];
    const float* z_b    = (const float*)d_in[21];
    const float* dim_w  = (const float*)d_in[22];
    const float* dim_b  = (const float*)d_in[23];
    const float* yaw_w  = (const float*)d_in[24];
    const float* yaw_b  = (const float*)d_in[25];
    const float* vel_w  = (const float*)d_in[26];
    const float* vel_b  = (const float*)d_in[27];

    float* out    = (float*)d_out;
    float* out_pf = out;
    float* out_pa = out + PA_OFF;
    float* out_sc = out + SC_OFF;

    dim3 ggrid(16, 4, 36);

    // ---- conv1: bev -> g_feat
    wino_wg<<<256, 256>>>(shared_w);
    wino_in<0><<<4096, 256>>>(bev);
    wino_gemm<<<ggrid, 256>>>();
    wino_out<0><<<4096, 256>>>(bn1g, bn1b, bn1m, bn1v, nullptr);

    // ---- conv2: g_feat -> heatmap logits (input resolved in DEVICE code)
    wino_wg<<<256, 256>>>(obj_w1);
    wino_in<1><<<4096, 256>>>(nullptr);
    wino_gemm<<<ggrid, 256>>>();
    wino_out<1><<<4096, 256>>>(bn2g, bn2b, bn2m, bn2v, obj_w2);
    red_kernel<<<256, 256>>>();

    // ---- topk + head
    topk_kernel<<<NB, 1024>>>(obj_b2, out_sc);
    head_kernel<<<NB*KTOP, 256>>>(anchors, fp_w1, fp_b1, ln_g, ln_b, fp_w2, fp_b2,
                                  z_w, z_b, dim_w, dim_b, yaw_w, yaw_b, vel_w, vel_b,
                                  out_pf, out_pa, out_sc);
}

// round 17
// speedup vs baseline: 4.1436x; 1.0872x over previous
#include <cuda_runtime.h>
#include <math.h>
#include <stdint.h>

// ---------------- problem constants ----------------
#define CC   256
#define HH   128
#define WW   128
#define NB   4
#define HWW  (HH*WW)
#define KTOP 100
#define NTIL4 1024                 // 32x32 tiles per image (4x4 outputs each)
#define TJ4   (NB*NTIL4)           // 4096 tile-columns
#define PPL4  ((size_t)CC*TJ4)     // 1,048,576 floats per plane

// output layout
#define PF_ELEMS (NB*KTOP*CC)
#define PA_OFF   PF_ELEMS
#define SC_OFF   (PF_ELEMS + NB*KTOP*11)

typedef unsigned long long ull;

// ---------------- scratch ----------------
__device__ float g_U[36*CC*CC];           // 9.4 MB  [p][oc][ic]
__device__ float g_V[36*CC*TJ4];          // 151 MB  [p][ic][tj]
__device__ float g_M[36*CC*TJ4];          // 151 MB  [p][oc][tj]
__device__ float g_H[(size_t)CC*NB*HWW];  // 67 MB   [oc][b][pix] (relu*w2)
__device__ float g_feat[(size_t)NB*CC*HWW];
__device__ float g_plog[NB*HWW];
__device__ int   g_tidx[NB*KTOP];

// ---------------- helpers ----------------
__device__ __forceinline__ ull ffma2(ull a, ull b, ull c) {
    ull d;
    asm("fma.rn.f32x2 %0, %1, %2, %3;" : "=l"(d) : "l"(a), "l"(b), "l"(c));
    return d;
}
__device__ __forceinline__ ull dupf(float v) {
    unsigned u = __float_as_uint(v);
    return ((ull)u << 32) | u;
}
__device__ __forceinline__ float lo32(ull a) { return __uint_as_float((unsigned)a); }
__device__ __forceinline__ float hi32(ull a) { return __uint_as_float((unsigned)(a >> 32)); }
__device__ __forceinline__ uint32_t smem_u32(const void* p) {
    uint32_t a;
    asm("{ .reg .u64 t; cvta.to.shared.u64 t, %1; cvt.u32.u64 %0, t; }" : "=r"(a) : "l"(p));
    return a;
}
__device__ __forceinline__ void cp16(uint32_t saddr, const void* gaddr) {
    asm volatile("cp.async.cg.shared.global [%0], [%1], 16;" :: "r"(saddr), "l"(gaddr) : "memory");
}
#define CP_COMMIT() asm volatile("cp.async.commit_group;" ::: "memory")
#define CP_WAIT(N)  asm volatile("cp.async.wait_group %0;" :: "n"(N) : "memory")

// G rows (F(4,3))
__device__ __forceinline__ void gmul(float a, float b, float c, float* o) {
    const float s6 = 1.f/6.f, s12 = 1.f/12.f, s24 = 1.f/24.f;
    o[0] = 0.25f*a;
    o[1] = -s6*(a + b + c);
    o[2] = -s6*(a - b + c);
    o[3] = s24*a + s12*b + s6*c;
    o[4] = s24*a - s12*b + s6*c;
    o[5] = c;
}
__device__ __forceinline__ void btmul(const float* a, float* o) {
    o[0] = 4.f*a[0] - 5.f*a[2] + a[4];
    o[1] = -4.f*a[1] - 4.f*a[2] + a[3] + a[4];
    o[2] =  4.f*a[1] - 4.f*a[2] - a[3] + a[4];
    o[3] = -2.f*a[1] - a[2] + 2.f*a[3] + a[4];
    o[4] =  2.f*a[1] - a[2] - 2.f*a[3] + a[4];
    o[5] =  4.f*a[1] - 5.f*a[3] + a[5];
}
__device__ __forceinline__ void atmul(const float* a, float* o) {
    o[0] = a[0] + a[1] + a[2] + a[3] + a[4];
    o[1] = a[1] - a[2] + 2.f*a[3] - 2.f*a[4];
    o[2] = a[1] + a[2] + 4.f*a[3] + 4.f*a[4];
    o[3] = a[1] - a[2] + 8.f*a[3] - 8.f*a[4] + a[5];
}

// ---------------- K0: weight transform U = G g G^T (6x6) ----------------
__global__ __launch_bounds__(256)
void wino_wg(const float* __restrict__ w)
{
    int idx = blockIdx.x*256 + threadIdx.x;  // oc*256+ic
    const float* g = w + (size_t)idx*9;
    float q[9];
    #pragma unroll
    for (int i = 0; i < 9; i++) q[i] = g[i];
    float u[6][3];
    #pragma unroll
    for (int c = 0; c < 3; c++) {
        float col[6];
        gmul(q[c], q[3+c], q[6+c], col);
        #pragma unroll
        for (int i = 0; i < 6; i++) u[i][c] = col[i];
    }
    #pragma unroll
    for (int i = 0; i < 6; i++) {
        float row[6];
        gmul(u[i][0], u[i][1], u[i][2], row);
        #pragma unroll
        for (int j = 0; j < 6; j++)
            g_U[(size_t)(i*6+j)*65536 + idx] = row[j];
    }
}

// ---------------- K1: input transform V = B^T d B ----------------
template<int MODE>
__global__ __launch_bounds__(256)
void wino_in(const float* __restrict__ in)
{
    int idx = blockIdx.x*256 + threadIdx.x;  // 1,048,576
    int tile = idx & 1023;
    int plane = idx >> 10;
    int ty = tile >> 5, tx5 = tile & 31;
    int b = plane >> 8, ic = plane & 255;
    const float* base_in = (MODE == 0) ? in : (const float*)g_feat;
    const float* src = base_in + (size_t)plane * HWW;
    int y0 = 4*ty - 1, x0 = 4*tx5 - 1;

    float d[6][6];
    #pragma unroll
    for (int r = 0; r < 6; r++) {
        int y = y0 + r;
        #pragma unroll
        for (int c2 = 0; c2 < 6; c2++) {
            int x = x0 + c2;
            d[r][c2] = ((unsigned)y < 128u && (unsigned)x < 128u) ? src[y*WW + x] : 0.f;
        }
    }
    float t[6][6];
    #pragma unroll
    for (int c2 = 0; c2 < 6; c2++) {
        float col[6] = {d[0][c2], d[1][c2], d[2][c2], d[3][c2], d[4][c2], d[5][c2]};
        float o[6];
        btmul(col, o);
        #pragma unroll
        for (int i = 0; i < 6; i++) t[i][c2] = o[i];
    }
    size_t tj = (size_t)b*NTIL4 + tile;
    #pragma unroll
    for (int i = 0; i < 6; i++) {
        float o[6];
        btmul(t[i], o);
        #pragma unroll
        for (int j = 0; j < 6; j++)
            g_V[(size_t)(i*6+j)*PPL4 + (size_t)ic*TJ4 + tj] = o[j];
    }
}

// ---------------- K2: 36 batched GEMMs, cp.async double-buffered ----------
// CTA: 64 oc x 256 tj, K=256 in 16 chunks. grid (tb=16, ocb=4, p=36).
// Thread: 8 oc x 4 tj-pairs (f32x2 lanes = adjacent tj). Warp = 8 oc x 256 tj.
__global__ __launch_bounds__(256, 2)
void wino_gemm()
{
    // s_V: 2 x 16k x 256 floats (plain) = 32 KB; s_Ud: 2 x 16k x 64 ull = 16 KB
    __shared__ __align__(16) float s_V[2][16*256];
    __shared__ __align__(16) ull   s_Ud[2][16*64];

    const int tx = threadIdx.x;
    const int tb = blockIdx.x, ocb = blockIdx.y, p = blockIdx.z;
    const int lane = tx & 31, wid = tx >> 5;

    const size_t pV = (size_t)p * PPL4 + tb*256;
    const float* uB = g_U + (size_t)p*65536 + (size_t)(ocb*64)*256;

    // staging decomposition
    const int v_k  = tx >> 4;          // 0..15 (k row)
    const int v_c4 = tx & 15;          // 0..15 (float4 col; 16 per row covers 64 floats... )
    // 16 rows x 64 float4/row = 1024 float4; thread does 4: (v_k, v_c4 + 16*i)
    const int u_oc = tx >> 2;          // 0..63
    const int u_kq = tx & 3;           // 0..3 (4 consecutive k)

    ull acc[8][4];
    #pragma unroll
    for (int j = 0; j < 8; j++)
        #pragma unroll
        for (int kk = 0; kk < 4; kk++) acc[j][kk] = 0ull;

    // ---- stage chunk 0
    {
        const int buf = 0, k0 = 0;
        #pragma unroll
        for (int i = 0; i < 4; i++) {
            int c4 = v_c4 + 16*i;
            cp16(smem_u32(&s_V[buf][v_k*256 + c4*4]), g_V + pV + (size_t)(k0 + v_k)*TJ4 + c4*4);
        }
        float4 w4 = *(const float4*)(uB + (size_t)u_oc*256 + k0 + 4*u_kq);
        s_Ud[buf][(u_kq*4+0)*64 + u_oc] = dupf(w4.x);
        s_Ud[buf][(u_kq*4+1)*64 + u_oc] = dupf(w4.y);
        s_Ud[buf][(u_kq*4+2)*64 + u_oc] = dupf(w4.z);
        s_Ud[buf][(u_kq*4+3)*64 + u_oc] = dupf(w4.w);
        CP_COMMIT();
    }

    #pragma unroll 1
    for (int c = 0; c < 16; c++) {
        const int buf = c & 1;
        // stage next chunk into other buffer (overlaps with this chunk's compute)
        if (c < 15) {
            const int nb = buf ^ 1, k0 = (c+1)*16;
            #pragma unroll
            for (int i = 0; i < 4; i++) {
                int c4 = v_c4 + 16*i;
                cp16(smem_u32(&s_V[nb][v_k*256 + c4*4]), g_V + pV + (size_t)(k0 + v_k)*TJ4 + c4*4);
            }
            float4 w4 = *(const float4*)(uB + (size_t)u_oc*256 + k0 + 4*u_kq);
            s_Ud[nb][(u_kq*4+0)*64 + u_oc] = dupf(w4.x);
            s_Ud[nb][(u_kq*4+1)*64 + u_oc] = dupf(w4.y);
            s_Ud[nb][(u_kq*4+2)*64 + u_oc] = dupf(w4.z);
            s_Ud[nb][(u_kq*4+3)*64 + u_oc] = dupf(w4.w);
            CP_COMMIT();
            CP_WAIT(1);          // chunk c's data complete
        } else {
            CP_WAIT(0);
        }
        __syncthreads();

        #pragma unroll
        for (int k = 0; k < 16; k++) {
            ull wd[8];
            const ull* wrow = &s_Ud[buf][k*64 + wid*8];
            #pragma unroll
            for (int j = 0; j < 8; j++) wd[j] = wrow[j];    // broadcast
            #pragma unroll
            for (int kk = 0; kk < 4; kk++) {
                ull vp = *(const ull*)&s_V[buf][k*256 + 2*(lane + 32*kk)];
                #pragma unroll
                for (int j = 0; j < 8; j++)
                    acc[j][kk] = ffma2(vp, wd[j], acc[j][kk]);
            }
        }
        __syncthreads();         // all done with buf before it is re-staged
    }

    #pragma unroll
    for (int j = 0; j < 8; j++) {
        int oc = ocb*64 + wid*8 + j;
        #pragma unroll
        for (int kk = 0; kk < 4; kk++) {
            float2 v = make_float2(lo32(acc[j][kk]), hi32(acc[j][kk]));
            *(float2*)&g_M[(size_t)p*PPL4 + (size_t)oc*TJ4 + tb*256 + 2*(lane + 32*kk)] = v;
        }
    }
}

// ---------------- K3: inverse transform Y = A^T M A + BN + ReLU ----------------
template<int MODE>
__global__ __launch_bounds__(256)
void wino_out(const float* __restrict__ bg, const float* __restrict__ bb,
              const float* __restrict__ bmn, const float* __restrict__ bv,
              const float* __restrict__ w2)
{
    int idx = blockIdx.x*256 + threadIdx.x;  // 1,048,576
    int tile = idx & 1023;
    int rest = idx >> 10;
    int oc = rest & 255, b = rest >> 8;
    size_t base = (size_t)oc*TJ4 + (size_t)b*NTIL4 + tile;

    float m[6][6];
    #pragma unroll
    for (int r = 0; r < 6; r++)
        #pragma unroll
        for (int c2 = 0; c2 < 6; c2++)
            m[r][c2] = g_M[(size_t)(r*6+c2)*PPL4 + base];

    float t[4][6];
    #pragma unroll
    for (int c2 = 0; c2 < 6; c2++) {
        float col[6] = {m[0][c2], m[1][c2], m[2][c2], m[3][c2], m[4][c2], m[5][c2]};
        float o[4];
        atmul(col, o);
        #pragma unroll
        for (int i = 0; i < 4; i++) t[i][c2] = o[i];
    }

    float scl = bg[oc] * rsqrtf(bv[oc] + 1e-5f);
    float bi  = bb[oc] - bmn[oc] * scl;
    float wv = (MODE == 1) ? w2[oc] : 1.f;

    int ty = tile >> 5, tx5 = tile & 31;
    int y = 4*ty, x = 4*tx5;
    float* dstb = (MODE == 0)
        ? g_feat + ((size_t)b*CC + oc)*HWW + (size_t)y*WW + x
        : g_H    + ((size_t)oc*NB + b)*HWW + (size_t)y*WW + x;

    #pragma unroll
    for (int i = 0; i < 4; i++) {
        float o[4];
        atmul(t[i], o);
        float4 v;
        v.x = fmaxf(o[0]*scl + bi, 0.f);
        v.y = fmaxf(o[1]*scl + bi, 0.f);
        v.z = fmaxf(o[2]*scl + bi, 0.f);
        v.w = fmaxf(o[3]*scl + bi, 0.f);
        if (MODE == 1) { v.x *= wv; v.y *= wv; v.z *= wv; v.w *= wv; }
        *(float4*)(dstb + (size_t)i*WW) = v;
    }
}

// ---------------- K4: heatmap logit = sum over oc (fixed order) ----------------
__global__ __launch_bounds__(256)
void red_kernel()
{
    int idx = blockIdx.x*256 + threadIdx.x;   // 65536
    int b = idx >> 14, pix = idx & 16383;
    float s = 0.f;
    #pragma unroll 8
    for (int oc = 0; oc < CC; oc++)
        s += g_H[((size_t)oc*NB + b)*HWW + pix];
    g_plog[b*HWW + pix] = s;
}

// ---------------- top-k (exact jax.lax.top_k semantics) ----------------
__global__ __launch_bounds__(1024)
void topk_kernel(const float* __restrict__ b2, float* __restrict__ out_sc)
{
    const int b    = blockIdx.x;
    const int tx   = threadIdx.x;
    const int lane = tx & 31, warp = tx >> 5;

    unsigned long long key[16];
    float lg[16];
    unsigned live = 0xFFFFu;
    const float bias = b2[0];

    #pragma unroll
    for (int k = 0; k < 16; k++) {
        int pix = tx + 1024*k;
        float v = g_plog[b*HWW + pix] + bias;
        lg[k] = v;
        unsigned u = __float_as_uint(v);
        u = (u & 0x80000000u) ? ~u : (u | 0x80000000u);
        key[k] = ((unsigned long long)u << 32) | (unsigned)(0xFFFFFFFFu - (unsigned)pix);
    }

    __shared__ unsigned long long s_wmax[32];
    __shared__ unsigned long long s_best;

    for (int r = 0; r < KTOP; r++) {
        unsigned long long m = 0ull;
        #pragma unroll
        for (int k = 0; k < 16; k++)
            if (live & (1u << k)) { if (key[k] > m) m = key[k]; }
        #pragma unroll
        for (int off = 16; off; off >>= 1) {
            unsigned long long o2 = __shfl_down_sync(0xFFFFFFFFu, m, off);
            if (o2 > m) m = o2;
        }
        if (lane == 0) s_wmax[warp] = m;
        __syncthreads();
        if (warp == 0) {
            unsigned long long mm = s_wmax[lane];
            #pragma unroll
            for (int off = 16; off; off >>= 1) {
                unsigned long long o2 = __shfl_down_sync(0xFFFFFFFFu, mm, off);
                if (o2 > mm) mm = o2;
            }
            if (lane == 0) s_best = mm;
        }
        __syncthreads();
        unsigned long long best = s_best;
        #pragma unroll
        for (int k = 0; k < 16; k++) {
            if ((live & (1u << k)) && key[k] == best) {
                live &= ~(1u << k);
                int pix = tx + 1024*k;
                g_tidx[b*KTOP + r]  = pix;
                out_sc[b*KTOP + r] = 1.0f / (1.0f + expf(-lg[k]));
            }
        }
        __syncthreads();
    }
}

// ---------------- per-query head (thread-per-output GEMV) ----------------
__global__ __launch_bounds__(256)
void head_kernel(const float* __restrict__ anchors,
                 const float* __restrict__ w1, const float* __restrict__ b1,
                 const float* __restrict__ lng, const float* __restrict__ lnb,
                 const float* __restrict__ w2, const float* __restrict__ b2,
                 const float* __restrict__ zw, const float* __restrict__ zb,
                 const float* __restrict__ dw, const float* __restrict__ db,
                 const float* __restrict__ yw, const float* __restrict__ yb,
                 const float* __restrict__ vw, const float* __restrict__ vb,
                 float* __restrict__ out_pf, float* __restrict__ out_pa,
                 const float* __restrict__ out_sc)
{
    const int q = blockIdx.x;
    const int b = q / KTOP, kq = q - b*KTOP;
    const int tx = threadIdx.x, lane = tx & 31, warp = tx >> 5;

    __shared__ float s_g[CC], s_x[CC], s_h[8], s_red[16];

    const int idx = g_tidx[q];
    s_g[tx] = g_feat[((size_t)b*CC + tx)*HWW + idx];
    __syncthreads();

    // GEMV1: output j = tx; 4 interleaved accumulators, fixed combine order
    {
        const float* wr = w1 + (size_t)tx*CC;
        float a0 = 0.f, a1 = 0.f, a2 = 0.f, a3 = 0.f;
        #pragma unroll 8
        for (int k = 0; k < CC; k += 4) {
            float4 w4 = *(const float4*)(wr + k);
            a0 += w4.x * s_g[k];
            a1 += w4.y * s_g[k+1];
            a2 += w4.z * s_g[k+2];
            a3 += w4.w * s_g[k+3];
        }
        float r = ((a0 + a1) + a2) + a3;
        __syncthreads();
        s_x[tx] = r + b1[tx];
    }
    __syncthreads();

    // LayerNorm over 256
    float v = s_x[tx];
    float s1 = v, s2 = v*v;
    #pragma unroll
    for (int off = 16; off; off >>= 1) {
        s1 += __shfl_xor_sync(0xFFFFFFFFu, s1, off);
        s2 += __shfl_xor_sync(0xFFFFFFFFu, s2, off);
    }
    if (lane == 0) { s_red[warp] = s1; s_red[8 + warp] = s2; }
    __syncthreads();
    float t1 = 0.f, t2 = 0.f;
    #pragma unroll
    for (int w3 = 0; w3 < 8; w3++) { t1 += s_red[w3]; t2 += s_red[8 + w3]; }
    float mu  = t1 * (1.0f/CC);
    float var = t2 * (1.0f/CC) - mu*mu;
    float rstd = rsqrtf(var + 1e-5f);
    float xn = (v - mu) * rstd * lng[tx] + lnb[tx];
    __syncthreads();
    s_x[tx] = fmaxf(xn, 0.f);
    __syncthreads();

    // GEMV2 + score scale
    {
        float sc = 1.f + out_sc[q];
        const float* wr = w2 + (size_t)tx*CC;
        float a0 = 0.f, a1 = 0.f, a2 = 0.f, a3 = 0.f;
        #pragma unroll 8
        for (int k = 0; k < CC; k += 4) {
            float4 w4 = *(const float4*)(wr + k);
            a0 += w4.x * s_x[k];
            a1 += w4.y * s_x[k+1];
            a2 += w4.z * s_x[k+2];
            a3 += w4.w * s_x[k+3];
        }
        float r = ((a0 + a1) + a2) + a3;
        out_pf[(size_t)q*CC + tx] = (r + b2[tx]) * sc;
    }

    // small heads: one per warp
    const float* hw; float hb;
    if (warp == 0)      { hw = zw;                  hb = zb[0]; }
    else if (warp < 4)  { hw = dw + (warp-1)*CC;    hb = db[warp-1]; }
    else if (warp < 6)  { hw = yw + (warp-4)*CC;    hb = yb[warp-4]; }
    else                { hw = vw + (warp-6)*CC;    hb = vb[warp-6]; }
    float pp = 0.f;
    #pragma unroll
    for (int m2 = 0; m2 < 8; m2++) pp += hw[lane + 32*m2] * s_g[lane + 32*m2];
    #pragma unroll
    for (int off = 16; off; off >>= 1) pp += __shfl_down_sync(0xFFFFFFFFu, pp, off);
    if (lane == 0) s_h[warp] = pp + hb;
    __syncthreads();

    if (tx == 0) {
        const float* pa = anchors + ((size_t)b*900 + kq)*11;
        float zp = s_h[0];
        float d0 = s_h[1], d1 = s_h[2], d2 = s_h[3];
        float y0 = tanhf(s_h[4]), y1 = tanhf(s_h[5]);
        float nrm = fmaxf(sqrtf(y0*y0 + y1*y1), 1e-6f);
        float ve0 = s_h[6], ve1 = s_h[7];
        int xs = idx & (WW-1), ys = idx >> 7;
        float* oa = out_pa + (size_t)q*11;
        oa[0]  = ((float)xs + 0.5f) * 0.8f + (-51.2f);
        oa[1]  = ((float)ys + 0.5f) * 0.8f + (-51.2f);
        oa[2]  = pa[2] + 0.5f * zp;
        oa[3]  = pa[3] + 0.2f * fminf(fmaxf(d0, -1.f), 1.f);
        oa[4]  = pa[4] + 0.2f * fminf(fmaxf(d1, -1.f), 1.f);
        oa[5]  = pa[5] + 0.2f * fminf(fmaxf(d2, -1.f), 1.f);
        oa[6]  = 0.7f*pa[6] + 0.3f*(y0 / nrm);
        oa[7]  = 0.7f*pa[7] + 0.3f*(y1 / nrm);
        oa[8]  = pa[8] + 0.2f * fminf(fmaxf(ve0, -2.f), 2.f);
        oa[9]  = pa[9] + 0.2f * fminf(fmaxf(ve1, -2.f), 2.f);
        oa[10] = pa[10];
    }
}

// ---------------- launch ----------------
extern "C" void kernel_launch(void* const* d_in, const int* in_sizes, int n_in,
                              void* d_out, int out_size)
{
    const float* bev      = (const float*)d_in[0];
    const float* anchors  = (const float*)d_in[1];
    const float* shared_w = (const float*)d_in[2];
    const float* bn1g = (const float*)d_in[3];
    const float* bn1b = (const float*)d_in[4];
    const float* bn1m = (const float*)d_in[5];
    const float* bn1v = (const float*)d_in[6];
    const float* obj_w1 = (const float*)d_in[7];
    const float* bn2g = (const float*)d_in[8];
    const float* bn2b = (const float*)d_in[9];
    const float* bn2m = (const float*)d_in[10];
    const float* bn2v = (const float*)d_in[11];
    const float* obj_w2 = (const float*)d_in[12];
    const float* obj_b2 = (const float*)d_in[13];
    const float* fp_w1  = (const float*)d_in[14];
    const float* fp_b1  = (const float*)d_in[15];
    const float* ln_g   = (const float*)d_in[16];
    const float* ln_b   = (const float*)d_in[17];
    const float* fp_w2  = (const float*)d_in[18];
    const float* fp_b2  = (const float*)d_in[19];
    const float* z_w    = (const float*)d_in[20];
    const float* z_b    = (const float*)d_in[21];
    const float* dim_w  = (const float*)d_in[22];
    const float* dim_b  = (const float*)d_in[23];
    const float* yaw_w  = (const float*)d_in[24];
    const float* yaw_b  = (const float*)d_in[25];
    const float* vel_w  = (const float*)d_in[26];
    const float* vel_b  = (const float*)d_in[27];

    float* out    = (float*)d_out;
    float* out_pf = out;
    float* out_pa = out + PA_OFF;
    float* out_sc = out + SC_OFF;

    dim3 ggrid(16, 4, 36);

    // ---- conv1: bev -> g_feat
    wino_wg<<<256, 256>>>(shared_w);
    wino_in<0><<<4096, 256>>>(bev);
    wino_gemm<<<ggrid, 256>>>();
    wino_out<0><<<4096, 256>>>(bn1g, bn1b, bn1m, bn1v, nullptr);

    // ---- conv2: g_feat -> heatmap logits (input resolved in DEVICE code)
    wino_wg<<<256, 256>>>(obj_w1);
    wino_in<1><<<4096, 256>>>(nullptr);
    wino_gemm<<<ggrid, 256>>>();
    wino_out<1><<<4096, 256>>>(bn2g, bn2b, bn2m, bn2v, obj_w2);
    red_kernel<<<256, 256>>>();

    // ---- topk + head
    topk_kernel<<<NB, 1024>>>(obj_b2, out_sc);
    head_kernel<<<NB*KTOP, 256>>>(anchors, fp_w1, fp_b1, ln_g, ln_b, fp_w2, fp_b2,
                                  z_w, z_b, dim_w, dim_b, yaw_w, yaw_b, vel_w, vel_b,
                                  out_pf, out_pa, out_sc);
}